// round 15
// baseline (speedup 1.0000x reference)
#include <cuda_runtime.h>
#include <cuda_fp16.h>

#define EPSF 1e-5f

namespace {
constexpr int NBLK = 1024;
constexpr int THREADS = 256;
// units = halves unless noted
constexpr int CTXP = 72;
constexpr int WP   = 72;
constexpr int BP   = 72;
constexpr int PC1  = 136;
constexpr int FP   = 72;
constexpr int HS   = 64 * 72 + 8;
constexpr int OP   = 66;

constexpr int OFF_CTX = 0;
constexpr int OFF_W   = OFF_CTX + 256 * CTXP;
constexpr int OFF_W1  = OFF_W + 64 * WP;
constexpr int OFF_A   = OFF_W + 2 * 64 * WP;
constexpr int OFF_B   = OFF_A + 4 * HS;
constexpr int OFF_AB  = OFF_B + 64 * BP;
constexpr int SMEM_HALVES = OFF_AB + 2048;      // 105536 B (2 CTA/SM)
}

// fp16 weight scratch, converted once per launch
__device__ __half g_pw [4 * 64 * 128];   // [k][d][c]
__device__ __half g_wq [4 * 64 * 64];    // [i][e'][t]
__device__ __half g_wk [4 * 64 * 64];    // [i][e][t]
__device__ __half g_wv [4 * 64 * 64];    // [i][e][t]
__device__ __half g_wo [4 * 64 * 64];    // [i][e'][e]

__global__ void prep_weights(const float* __restrict__ proj_w, const float* __restrict__ wq,
                             const float* __restrict__ wk, const float* __restrict__ wv,
                             const float* __restrict__ wo) {
    int tid = blockIdx.x * blockDim.x + threadIdx.x;
    int stride = gridDim.x * blockDim.x;
    for (int idx = tid; idx < 32768; idx += stride) g_pw[idx] = __float2half_rn(proj_w[idx]);
    for (int idx = tid; idx < 16384; idx += stride) {
        g_wq[idx] = __float2half_rn(wq[idx]);
        g_wk[idx] = __float2half_rn(wk[idx]);
        g_wv[idx] = __float2half_rn(wv[idx]);
        g_wo[idx] = __float2half_rn(wo[idx]);
    }
}

__device__ __forceinline__ float warp_sum(float v) {
#pragma unroll
    for (int o = 16; o; o >>= 1) v += __shfl_xor_sync(0xffffffffu, v, o);
    return v;
}
__device__ __forceinline__ void mma16(float4& c, unsigned a0, unsigned a1, unsigned a2, unsigned a3,
                                      unsigned b0, unsigned b1) {
    asm volatile("mma.sync.aligned.m16n8k16.row.col.f32.f16.f16.f32 "
                 "{%0,%1,%2,%3}, {%4,%5,%6,%7}, {%8,%9}, {%0,%1,%2,%3};\n"
                 : "+f"(c.x), "+f"(c.y), "+f"(c.z), "+f"(c.w)
                 : "r"(a0), "r"(a1), "r"(a2), "r"(a3), "r"(b0), "r"(b1));
}
__device__ __forceinline__ void sth2(__half* p, float x, float y) {
    *reinterpret_cast<__half2*>(p) = __floats2half2_rn(x, y);
}
__device__ __forceinline__ unsigned sptr(const void* p) {
    return (unsigned)__cvta_generic_to_shared(p);
}
__device__ __forceinline__ void ldsm4(unsigned& r0, unsigned& r1, unsigned& r2, unsigned& r3, unsigned addr) {
    asm volatile("ldmatrix.sync.aligned.m8n8.x4.shared.b16 {%0,%1,%2,%3}, [%4];"
                 : "=r"(r0), "=r"(r1), "=r"(r2), "=r"(r3) : "r"(addr));
}
__device__ __forceinline__ void ldsm4t(unsigned& r0, unsigned& r1, unsigned& r2, unsigned& r3, unsigned addr) {
    asm volatile("ldmatrix.sync.aligned.m8n8.x4.trans.shared.b16 {%0,%1,%2,%3}, [%4];"
                 : "=r"(r0), "=r"(r1), "=r"(r2), "=r"(r3) : "r"(addr));
}
__device__ __forceinline__ __half2 h2u(unsigned u) { return *reinterpret_cast<__half2*>(&u); }
__device__ __forceinline__ unsigned hpack(__half2 h) { return *reinterpret_cast<unsigned*>(&h); }

__device__ __forceinline__ void cpa16(unsigned s, const void* g) {
    asm volatile("cp.async.ca.shared.global [%0], [%1], 16;" :: "r"(s), "l"(g) : "memory");
}
#define CPA_COMMIT   asm volatile("cp.async.commit_group;" ::: "memory")
#define CPA_WAIT_ALL asm volatile("cp.async.wait_group 0;" ::: "memory")

__device__ __forceinline__ void stage_slot_async(__half* slot, const __half* g, int tid) {
#pragma unroll
    for (int idx = tid; idx < 512; idx += THREADS) {
        int e = idx >> 3, q = idx & 7;
        cpa16(sptr(slot + e * WP) + q * 16, g + idx * 8);
    }
}

__global__ __launch_bounds__(THREADS, 2)
void cma_fused(const float* __restrict__ feats,
               const float* __restrict__ proj_b, const float* __restrict__ bq,
               const float* __restrict__ bv, const float* __restrict__ bo,
               const float* __restrict__ ng, const float* __restrict__ nb,
               const float* __restrict__ tfw, const float* __restrict__ fg,
               const float* __restrict__ fb, float* __restrict__ out)
{
    extern __shared__ __half smh[];
    __half* sctx  = smh + OFF_CTX;
    __half* slot0 = smh + OFF_W;
    __half* slot1 = smh + OFF_W1;
    __half* bufA  = smh + OFF_A;    // K, then AGG heads
    __half* bufB  = smh + OFF_B;
    float*  abuf  = reinterpret_cast<float*>(smh + OFF_AB);
    float*  obuf  = reinterpret_cast<float*>(smh + OFF_A);

    const int b    = blockIdx.x;
    const int tid  = threadIdx.x;
    const int lane = tid & 31;
    const int wid  = tid >> 5;    // 0..7
    const int lg   = lane >> 2;
    const int lt   = lane & 3;
    const int lm   = lane & 15;
    const int lk8  = (lane >> 4) * 8;

    float wgt[4];
    {
        float t0 = __ldg(tfw + 0), t1 = __ldg(tfw + 1), t2 = __ldg(tfw + 2), t3 = __ldg(tfw + 3);
        float tm = fmaxf(fmaxf(t0, t1), fmaxf(t2, t3));
        float e0 = __expf(t0 - tm), e1 = __expf(t1 - tm), e2 = __expf(t2 - tm), e3 = __expf(t3 - tm);
        float inv = 1.f / (e0 + e1 + e2 + e3);
        wgt[0] = e0 * inv; wgt[1] = e1 * inv; wgt[2] = e2 * inv; wgt[3] = e3 * inv;
    }

    // ========= Phase 1: proj -> sctx, software-pipelined at half-tile grain =========
    {
        __half* spw   = bufA;              // A: [d][c] pitch PC1
        __half* sfeat = bufA + 64 * PC1;   // B: [c][t] pitch FP, 128 rows
        const int m0 = 16 * (wid & 3);
        const int n0 = 32 * (wid >> 2);
        const unsigned aaddr = sptr(spw + (m0 + lm) * PC1 + lk8);
        const unsigned baddr = sptr(sfeat + lm * FP + n0 + lk8);

        // prologue: sfeat rows 0..63 of k=0 (direct), spw cols 0..63 of k=0 (async)
        {
            const float4* fgl = reinterpret_cast<const float4*>(feats + (size_t)b * 8192);
#pragma unroll
            for (int q4 = 0; q4 < 4; q4++) {
                int idx = tid + 256 * q4;
                float4 f = fgl[idx];
                int c = idx >> 4, q = idx & 15;
                uint2 v;
                v.x = hpack(__floats2half2_rn(f.x, f.y));
                v.y = hpack(__floats2half2_rn(f.z, f.w));
                *reinterpret_cast<uint2*>(sfeat + c * FP + 4 * q) = v;
            }
#pragma unroll
            for (int idx = tid; idx < 512; idx += THREADS) {
                int d = idx >> 3, q = idx & 7;
                cpa16(sptr(spw + d * PC1) + q * 16, g_pw + d * 128 + q * 8);
            }
            CPA_COMMIT;
            CPA_WAIT_ALL;
            __syncthreads();
        }

        for (int k = 0; k < 4; k++) {
            const float4* fgl = reinterpret_cast<const float4*>(feats + (size_t)(k * NBLK + b) * 8192);
            float4 acc[4] = {{0,0,0,0},{0,0,0,0},{0,0,0,0},{0,0,0,0}};
            float4 st[4];

            // ---- Block1: prefetch sfeat h1(k) + spw cols64..127(k); mma over h0 ----
#pragma unroll
            for (int q4 = 0; q4 < 4; q4++) st[q4] = fgl[1024 + tid + 256 * q4];
#pragma unroll
            for (int idx = tid; idx < 512; idx += THREADS) {
                int d = idx >> 3, q = idx & 7;
                cpa16(sptr(spw + d * PC1 + 64) + q * 16, g_pw + k * 8192 + d * 128 + 64 + q * 8);
            }
            CPA_COMMIT;
#pragma unroll
            for (int kk = 0; kk < 4; kk++) {
                int k0 = kk * 16;
                unsigned a0, a1, a2, a3, b0, b1, b2, b3, c0, c1, c2, c3;
                ldsm4(a0, a1, a2, a3, aaddr + k0 * 2);
                ldsm4t(b0, b1, b2, b3, baddr + k0 * (FP * 2));
                ldsm4t(c0, c1, c2, c3, baddr + k0 * (FP * 2) + 32);
                mma16(acc[0], a0, a1, a2, a3, b0, b1);
                mma16(acc[1], a0, a1, a2, a3, b2, b3);
                mma16(acc[2], a0, a1, a2, a3, c0, c1);
                mma16(acc[3], a0, a1, a2, a3, c2, c3);
            }
#pragma unroll
            for (int q4 = 0; q4 < 4; q4++) {
                int idx = tid + 256 * q4;
                int c = 64 + (idx >> 4), q = idx & 15;
                uint2 v;
                v.x = hpack(__floats2half2_rn(st[q4].x, st[q4].y));
                v.y = hpack(__floats2half2_rn(st[q4].z, st[q4].w));
                *reinterpret_cast<uint2*>(sfeat + c * FP + 4 * q) = v;
            }
            CPA_WAIT_ALL;
            __syncthreads();

            // ---- Block2: prefetch sfeat h0(k+1) + spw cols0..63(k+1); mma over h1 ----
            if (k < 3) {
                const float4* fglN = reinterpret_cast<const float4*>(feats + (size_t)((k + 1) * NBLK + b) * 8192);
#pragma unroll
                for (int q4 = 0; q4 < 4; q4++) st[q4] = fglN[tid + 256 * q4];
#pragma unroll
                for (int idx = tid; idx < 512; idx += THREADS) {
                    int d = idx >> 3, q = idx & 7;
                    cpa16(sptr(spw + d * PC1) + q * 16, g_pw + (k + 1) * 8192 + d * 128 + q * 8);
                }
                CPA_COMMIT;
            }
#pragma unroll
            for (int kk = 0; kk < 4; kk++) {
                int k0 = 64 + kk * 16;
                unsigned a0, a1, a2, a3, b0, b1, b2, b3, c0, c1, c2, c3;
                ldsm4(a0, a1, a2, a3, aaddr + k0 * 2);
                ldsm4t(b0, b1, b2, b3, baddr + k0 * (FP * 2));
                ldsm4t(c0, c1, c2, c3, baddr + k0 * (FP * 2) + 32);
                mma16(acc[0], a0, a1, a2, a3, b0, b1);
                mma16(acc[1], a0, a1, a2, a3, b2, b3);
                mma16(acc[2], a0, a1, a2, a3, c0, c1);
                mma16(acc[3], a0, a1, a2, a3, c2, c3);
            }
            if (k < 3) {
#pragma unroll
                for (int q4 = 0; q4 < 4; q4++) {
                    int idx = tid + 256 * q4;
                    int c = idx >> 4, q = idx & 15;
                    uint2 v;
                    v.x = hpack(__floats2half2_rn(st[q4].x, st[q4].y));
                    v.y = hpack(__floats2half2_rn(st[q4].z, st[q4].w));
                    *reinterpret_cast<uint2*>(sfeat + c * FP + 4 * q) = v;
                }
            }
            // epilogue: proj result -> sctx
            float pb0 = __ldg(proj_b + k * 64 + m0 + lg);
            float pb1 = __ldg(proj_b + k * 64 + m0 + lg + 8);
            __half* crow0 = sctx + (k * 64 + m0 + lg) * CTXP;
            __half* crow1 = crow0 + 8 * CTXP;
#pragma unroll
            for (int j = 0; j < 4; j++) {
                int col = n0 + 8 * j + 2 * lt;
                sth2(crow0 + col, acc[j].x + pb0, acc[j].y + pb0);
                sth2(crow1 + col, acc[j].z + pb1, acc[j].w + pb1);
            }
            if (k < 3) CPA_WAIT_ALL;
            __syncthreads();
        }
    }

    // prefetch i=0 weights: wq -> slot0, wk -> slot1
    stage_slot_async(slot0, g_wq, tid);
    stage_slot_async(slot1, g_wk, tid);
    CPA_COMMIT;
    CPA_WAIT_ALL;
    __syncthreads();

    // ================= Phase 2: per-model attention =================
    for (int i = 0; i < 4; i++) {
        // ======== Phase A: G1 (QP) + G2 (K) — independent, one barrier ========
        {
            // G1: QP[r][e'] = bq + q_in @ wq^T -> bufB (m16n32/warp)
            const int m0 = 16 * (wid & 3);
            const int n0 = 32 * (wid >> 2);
            int rA = m0 + lm;
            int jA = ((rA >> 4) << 6) + ((rA & 15) << 2) + i;
            const unsigned aaddr = sptr(sctx + jA * CTXP + lk8);
            const unsigned baddr0 = sptr(slot0 + (n0 + lm) * WP + lk8);
            const unsigned baddr1 = sptr(slot0 + (n0 + 16 + lm) * WP + lk8);
            float4 acc[4] = {{0,0,0,0},{0,0,0,0},{0,0,0,0},{0,0,0,0}};
#pragma unroll
            for (int k0 = 0; k0 < 64; k0 += 16) {
                unsigned a0, a1, a2, a3, p0, p1, p2, p3, q0, q1, q2, q3;
                ldsm4(a0, a1, a2, a3, aaddr + k0 * 2);
                ldsm4(p0, p1, p2, p3, baddr0 + k0 * 2);
                ldsm4(q0, q1, q2, q3, baddr1 + k0 * 2);
                mma16(acc[0], a0, a1, a2, a3, p0, p2);
                mma16(acc[1], a0, a1, a2, a3, p1, p3);
                mma16(acc[2], a0, a1, a2, a3, q0, q2);
                mma16(acc[3], a0, a1, a2, a3, q1, q3);
            }
            __half* crow0 = bufB + (m0 + lg) * BP;
            __half* crow1 = crow0 + 8 * BP;
#pragma unroll
            for (int j = 0; j < 4; j++) {
                int col = n0 + 8 * j + 2 * lt;
                float b0 = __ldg(bq + i * 64 + col), b1 = __ldg(bq + i * 64 + col + 1);
                sth2(crow0 + col, acc[j].x + b0, acc[j].y + b1);
                sth2(crow1 + col, acc[j].z + b0, acc[j].w + b1);
            }

            // G2: K[n][e] = ctx[n] @ wk^T -> bufA (A-frags hoisted once)
            const int warp_m = 32 * wid;
            const unsigned kaaddr0 = sptr(sctx + (warp_m + lm) * CTXP + lk8);
            const unsigned kaaddr1 = sptr(sctx + (warp_m + 16 + lm) * CTXP + lk8);
            unsigned af[2][4][4];
#pragma unroll
            for (int kk = 0; kk < 4; kk++) {
                ldsm4(af[0][kk][0], af[0][kk][1], af[0][kk][2], af[0][kk][3], kaaddr0 + kk * 32);
                ldsm4(af[1][kk][0], af[1][kk][1], af[1][kk][2], af[1][kk][3], kaaddr1 + kk * 32);
            }
#pragma unroll
            for (int nh = 0; nh < 2; nh++) {
                const unsigned kbA = sptr(slot1 + (32 * nh + lm) * WP + lk8);
                const unsigned kbB = sptr(slot1 + (32 * nh + 16 + lm) * WP + lk8);
                float4 kacc[2][4] = {{{0,0,0,0},{0,0,0,0},{0,0,0,0},{0,0,0,0}},
                                     {{0,0,0,0},{0,0,0,0},{0,0,0,0},{0,0,0,0}}};
#pragma unroll
                for (int kk = 0; kk < 4; kk++) {
                    unsigned p0, p1, p2, p3, q0, q1, q2, q3;
                    ldsm4(p0, p1, p2, p3, kbA + kk * 32);
                    ldsm4(q0, q1, q2, q3, kbB + kk * 32);
                    mma16(kacc[0][0], af[0][kk][0], af[0][kk][1], af[0][kk][2], af[0][kk][3], p0, p2);
                    mma16(kacc[0][1], af[0][kk][0], af[0][kk][1], af[0][kk][2], af[0][kk][3], p1, p3);
                    mma16(kacc[0][2], af[0][kk][0], af[0][kk][1], af[0][kk][2], af[0][kk][3], q0, q2);
                    mma16(kacc[0][3], af[0][kk][0], af[0][kk][1], af[0][kk][2], af[0][kk][3], q1, q3);
                    mma16(kacc[1][0], af[1][kk][0], af[1][kk][1], af[1][kk][2], af[1][kk][3], p0, p2);
                    mma16(kacc[1][1], af[1][kk][0], af[1][kk][1], af[1][kk][2], af[1][kk][3], p1, p3);
                    mma16(kacc[1][2], af[1][kk][0], af[1][kk][1], af[1][kk][2], af[1][kk][3], q0, q2);
                    mma16(kacc[1][3], af[1][kk][0], af[1][kk][1], af[1][kk][2], af[1][kk][3], q1, q3);
                }
#pragma unroll
                for (int mt = 0; mt < 2; mt++) {
                    __half* kc0 = bufA + (warp_m + 16 * mt + lg) * CTXP;
                    __half* kc1 = kc0 + 8 * CTXP;
#pragma unroll
                    for (int j = 0; j < 4; j++) {
                        int col = 32 * nh + 8 * j + 2 * lt;
                        sth2(kc0 + col, kacc[mt][j].x, kacc[mt][j].y);
                        sth2(kc1 + col, kacc[mt][j].z, kacc[mt][j].w);
                    }
                }
            }
        }
        __syncthreads();

        // ======== Phase B: prefetch wv->slot0, wo->slot1; G3a scores+softmax ========
        stage_slot_async(slot0, g_wv + i * 4096, tid);
        stage_slot_async(slot1, g_wo + i * 4096, tid);
        CPA_COMMIT;
#pragma unroll
        for (int p = 0; p < 4; p++) {
            int r   = wid * 8 + p * 2 + (lane >> 4);
            int sub = lane & 15;
            int h   = sub >> 2, kp = sub & 3;
            int j   = ((r >> 4) << 6) + ((r & 15) << 2) + kp;
            const uint4* q4 = reinterpret_cast<const uint4*>(bufB + r * BP + 16 * h);
            const uint4* k4 = reinterpret_cast<const uint4*>(bufA + j * CTXP + 16 * h);
            uint4 qa = q4[0], qb = q4[1];
            uint4 ka = k4[0], kb = k4[1];
            __half2 ac0 = __hmul2(h2u(qa.x), h2u(ka.x));
            __half2 ac1 = __hmul2(h2u(qa.y), h2u(ka.y));
            ac0 = __hfma2(h2u(qa.z), h2u(ka.z), ac0);
            ac1 = __hfma2(h2u(qa.w), h2u(ka.w), ac1);
            ac0 = __hfma2(h2u(qb.x), h2u(kb.x), ac0);
            ac1 = __hfma2(h2u(qb.y), h2u(kb.y), ac1);
            ac0 = __hfma2(h2u(qb.z), h2u(kb.z), ac0);
            ac1 = __hfma2(h2u(qb.w), h2u(kb.w), ac1);
            float2 f0 = __half22float2(ac0), f1 = __half22float2(ac1);
            float s = ((f0.x + f0.y) + (f1.x + f1.y)) * 0.25f;
            float m = fmaxf(s, __shfl_xor_sync(0xffffffffu, s, 1));
            m = fmaxf(m, __shfl_xor_sync(0xffffffffu, m, 2));
            float pe  = __expf(s - m);
            float den = pe + __shfl_xor_sync(0xffffffffu, pe, 1);
            den += __shfl_xor_sync(0xffffffffu, den, 2);
            abuf[r * 16 + sub] = pe / den;
        }
        CPA_WAIT_ALL;
        __syncthreads();

        // ======== Phase C: G3b AGG[h][r][t] = sum_kp a * ctx (uint4-wide) ========
        {
            const int rb = (tid >> 3) * 2;    // 0..62 step 2
            const int c8 = (tid & 7) * 8;     // 8-half column group
#pragma unroll
            for (int rr = 0; rr < 2; rr++) {
                int r  = rb + rr;
                int jb = ((r >> 4) << 6) + ((r & 15) << 2);
                uint4 cv[4];
#pragma unroll
                for (int kp = 0; kp < 4; kp++)
                    cv[kp] = *reinterpret_cast<const uint4*>(sctx + (jb + kp) * CTXP + c8);
                const float4* arow = reinterpret_cast<const float4*>(abuf + r * 16);
#pragma unroll
                for (int h = 0; h < 4; h++) {
                    float4 a4 = arow[h];
                    __half2 ac0 = __float2half2_rn(0.f), ac1 = ac0, ac2 = ac0, ac3 = ac0;
#pragma unroll
                    for (int kp = 0; kp < 4; kp++) {
                        __half2 ah = __float2half2_rn((&a4.x)[kp]);
                        ac0 = __hfma2(ah, h2u(cv[kp].x), ac0);
                        ac1 = __hfma2(ah, h2u(cv[kp].y), ac1);
                        ac2 = __hfma2(ah, h2u(cv[kp].z), ac2);
                        ac3 = __hfma2(ah, h2u(cv[kp].w), ac3);
                    }
                    uint4 ov;
                    ov.x = hpack(ac0); ov.y = hpack(ac1);
                    ov.z = hpack(ac2); ov.w = hpack(ac3);
                    *reinterpret_cast<uint4*>(bufA + h * HS + r * CTXP + c8) = ov;
                }
            }
        }
        __syncthreads();

        // ======== Phase D: G4 OA[r][e] = bv + AGG[h(e)] @ wv^T -> bufB (B hoisted) ========
        {
            const int h  = wid >> 1;
            const int mq = wid & 1;
            const unsigned baddr = sptr(slot0 + (16 * h + lm) * WP + lk8);
            const unsigned aaddr0 = sptr(bufA + h * HS + (32 * mq + lm) * CTXP + lk8);
            const unsigned aaddr1 = sptr(bufA + h * HS + (32 * mq + 16 + lm) * CTXP + lk8);
            float4 acc[2][2] = {{{0,0,0,0},{0,0,0,0}},{{0,0,0,0},{0,0,0,0}}};
#pragma unroll
            for (int k0 = 0; k0 < 64; k0 += 16) {
                unsigned p0, p1, p2, p3;
                ldsm4(p0, p1, p2, p3, baddr + k0 * 2);
                unsigned a0, a1, a2, a3;
                ldsm4(a0, a1, a2, a3, aaddr0 + k0 * 2);
                mma16(acc[0][0], a0, a1, a2, a3, p0, p2);
                mma16(acc[0][1], a0, a1, a2, a3, p1, p3);
                ldsm4(a0, a1, a2, a3, aaddr1 + k0 * 2);
                mma16(acc[1][0], a0, a1, a2, a3, p0, p2);
                mma16(acc[1][1], a0, a1, a2, a3, p1, p3);
            }
#pragma unroll
            for (int mt = 0; mt < 2; mt++) {
                const int m0 = 32 * mq + 16 * mt;
                __half* crow0 = bufB + (m0 + lg) * BP;
                __half* crow1 = crow0 + 8 * BP;
#pragma unroll
                for (int j = 0; j < 2; j++) {
                    int col = 16 * h + 8 * j + 2 * lt;
                    float b0 = __ldg(bv + i * 64 + col), b1 = __ldg(bv + i * 64 + col + 1);
                    sth2(crow0 + col, acc[mt][j].x + b0, acc[mt][j].y + b1);
                    sth2(crow1 + col, acc[mt][j].z + b0, acc[mt][j].w + b1);
                }
            }
        }
        __syncthreads();

        // ======== Phase E: G5 O[r][e'] = bo + OA @ wo^T -> obuf fp32 ========
        {
            const int m0 = 16 * (wid & 3);
            const int n0 = 32 * (wid >> 2);
            const unsigned aaddr  = sptr(bufB + (m0 + lm) * BP + lk8);
            const unsigned baddr0 = sptr(slot1 + (n0 + lm) * WP + lk8);
            const unsigned baddr1 = sptr(slot1 + (n0 + 16 + lm) * WP + lk8);
            float4 acc[4] = {{0,0,0,0},{0,0,0,0},{0,0,0,0},{0,0,0,0}};
#pragma unroll
            for (int k0 = 0; k0 < 64; k0 += 16) {
                unsigned a0, a1, a2, a3, p0, p1, p2, p3, q0, q1, q2, q3;
                ldsm4(a0, a1, a2, a3, aaddr + k0 * 2);
                ldsm4(p0, p1, p2, p3, baddr0 + k0 * 2);
                ldsm4(q0, q1, q2, q3, baddr1 + k0 * 2);
                mma16(acc[0], a0, a1, a2, a3, p0, p2);
                mma16(acc[1], a0, a1, a2, a3, p1, p3);
                mma16(acc[2], a0, a1, a2, a3, q0, q2);
                mma16(acc[3], a0, a1, a2, a3, q1, q3);
            }
            float* crow0 = obuf + (m0 + lg) * OP;
            float* crow1 = crow0 + 8 * OP;
#pragma unroll
            for (int j = 0; j < 4; j++) {
                int col = n0 + 8 * j + 2 * lt;
                float b0 = __ldg(bo + i * 64 + col), b1 = __ldg(bo + i * 64 + col + 1);
                crow0[col]     = acc[j].x + b0;
                crow0[col + 1] = acc[j].y + b1;
                crow1[col]     = acc[j].z + b0;
                crow1[col + 1] = acc[j].w + b1;
            }
        }
        __syncthreads();

        // ======== Phase F: LN-64 (+residual), vectorized; prefetch next wq/wk ========
        if (i < 3) {
            stage_slot_async(slot0, g_wq + (i + 1) * 4096, tid);
            stage_slot_async(slot1, g_wk + (i + 1) * 4096, tid);
            CPA_COMMIT;
        }
#pragma unroll
        for (int p = 0; p < 8; p++) {
            int r   = wid * 8 + p;
            int jqr = ((r >> 4) << 6) + ((r & 15) << 2) + i;
            __half2 sx = *reinterpret_cast<const __half2*>(sctx + jqr * CTXP + 2 * lane);
            float2  xo = *reinterpret_cast<const float2*>(obuf + r * OP + 2 * lane);
            float x0 = xo.x + __low2float(sx);
            float x1 = xo.y + __high2float(sx);
            float mean = warp_sum(x0 + x1) * (1.f / 64.f);
            float d0 = x0 - mean, d1 = x1 - mean;
            float var = warp_sum(d0 * d0 + d1 * d1) * (1.f / 64.f);
            float rs = rsqrtf(var + EPSF);
            float2 g2 = __ldg(reinterpret_cast<const float2*>(ng + i * 64 + 2 * lane));
            float2 b2 = __ldg(reinterpret_cast<const float2*>(nb + i * 64 + 2 * lane));
            float2 o;
            o.x = (d0 * rs * g2.x + b2.x) * wgt[i];
            o.y = (d1 * rs * g2.y + b2.y) * wgt[i];
            *reinterpret_cast<float2*>(out + (size_t)b * 16384 + r * 256 + i * 64 + 2 * lane) = o;
        }
        if (i < 3) CPA_WAIT_ALL;
        __syncthreads();
    }

    // ================= Phase 3: final LN over 256, in-place on out =================
    const float4* fg4 = reinterpret_cast<const float4*>(fg);
    const float4* fb4 = reinterpret_cast<const float4*>(fb);
#pragma unroll
    for (int p = 0; p < 8; p++) {
        int r = wid * 8 + p;
        float4* row4 = reinterpret_cast<float4*>(out + (size_t)b * 16384 + r * 256);
        float4 xa = row4[lane], xb = row4[lane + 32];
        float s = xa.x + xa.y + xa.z + xa.w + xb.x + xb.y + xb.z + xb.w;
        float mean = warp_sum(s) * (1.f / 256.f);
        xa.x -= mean; xa.y -= mean; xa.z -= mean; xa.w -= mean;
        xb.x -= mean; xb.y -= mean; xb.z -= mean; xb.w -= mean;
        float v = xa.x*xa.x + xa.y*xa.y + xa.z*xa.z + xa.w*xa.w
                + xb.x*xb.x + xb.y*xb.y + xb.z*xb.z + xb.w*xb.w;
        float var = warp_sum(v) * (1.f / 256.f);
        float rs = rsqrtf(var + EPSF);
        float4 ga = fg4[lane], gb = fg4[lane + 32];
        float4 ba = fb4[lane], bb = fb4[lane + 32];
        row4[lane]      = make_float4(fmaf(xa.x * rs, ga.x, ba.x), fmaf(xa.y * rs, ga.y, ba.y),
                                      fmaf(xa.z * rs, ga.z, ba.z), fmaf(xa.w * rs, ga.w, ba.w));
        row4[lane + 32] = make_float4(fmaf(xb.x * rs, gb.x, bb.x), fmaf(xb.y * rs, gb.y, bb.y),
                                      fmaf(xb.z * rs, gb.z, bb.z), fmaf(xb.w * rs, gb.w, bb.w));
    }
}

extern "C" void kernel_launch(void* const* d_in, const int* in_sizes, int n_in,
                              void* d_out, int out_size) {
    (void)in_sizes; (void)n_in; (void)out_size;
    const float* feats  = (const float*)d_in[0];
    const float* proj_w = (const float*)d_in[1];
    const float* proj_b = (const float*)d_in[2];
    const float* wq     = (const float*)d_in[3];
    const float* wk     = (const float*)d_in[4];
    const float* wv     = (const float*)d_in[5];
    const float* bq     = (const float*)d_in[6];
    const float* bv     = (const float*)d_in[8];
    const float* wo     = (const float*)d_in[9];
    const float* bo     = (const float*)d_in[10];
    const float* ng     = (const float*)d_in[11];
    const float* nb     = (const float*)d_in[12];
    const float* tfw    = (const float*)d_in[13];
    const float* fg     = (const float*)d_in[14];
    const float* fb     = (const float*)d_in[15];
    float* out = (float*)d_out;

    prep_weights<<<64, 256>>>(proj_w, wq, wk, wv, wo);

    size_t smem = SMEM_HALVES * sizeof(__half);
    cudaFuncSetAttribute(cma_fused, cudaFuncAttributeMaxDynamicSharedMemorySize, (int)smem);
    cma_fused<<<NBLK, THREADS, smem>>>(feats, proj_b, bq, bv, bo,
                                       ng, nb, tfw, fg, fb, out);
}

// round 16
// speedup vs baseline: 1.4335x; 1.4335x over previous
#include <cuda_runtime.h>
#include <cuda_fp16.h>

#define EPSF 1e-5f

namespace {
constexpr int NBLK = 1024;
constexpr int THREADS = 256;
// units = halves unless noted
constexpr int CTXP = 72;
constexpr int WP   = 72;
constexpr int BP   = 72;
constexpr int PC1  = 136;
constexpr int FP   = 72;
constexpr int HS   = 64 * 72 + 8;
constexpr int OP   = 66;

constexpr int OFF_CTX = 0;
constexpr int OFF_W   = OFF_CTX + 256 * CTXP;
constexpr int OFF_W1  = OFF_W + 64 * WP;
constexpr int OFF_A   = OFF_W + 2 * 64 * WP;
constexpr int OFF_B   = OFF_A + 4 * HS;
constexpr int OFF_AB  = OFF_B + 64 * BP;
constexpr int SMEM_HALVES = OFF_AB + 2048;      // 105536 B (2 CTA/SM)
}

// fp16 weight scratch, converted once per launch
__device__ __half g_pw [4 * 64 * 128];   // [k][d][c]
__device__ __half g_wq [4 * 64 * 64];    // [i][e'][t]
__device__ __half g_wk [4 * 64 * 64];    // [i][e][t]
__device__ __half g_wv [4 * 64 * 64];    // [i][e][t]
__device__ __half g_wo [4 * 64 * 64];    // [i][e'][e]

__global__ void prep_weights(const float* __restrict__ proj_w, const float* __restrict__ wq,
                             const float* __restrict__ wk, const float* __restrict__ wv,
                             const float* __restrict__ wo) {
    int tid = blockIdx.x * blockDim.x + threadIdx.x;
    int stride = gridDim.x * blockDim.x;
    for (int idx = tid; idx < 32768; idx += stride) g_pw[idx] = __float2half_rn(proj_w[idx]);
    for (int idx = tid; idx < 16384; idx += stride) {
        g_wq[idx] = __float2half_rn(wq[idx]);
        g_wk[idx] = __float2half_rn(wk[idx]);
        g_wv[idx] = __float2half_rn(wv[idx]);
        g_wo[idx] = __float2half_rn(wo[idx]);
    }
}

__device__ __forceinline__ float warp_sum(float v) {
#pragma unroll
    for (int o = 16; o; o >>= 1) v += __shfl_xor_sync(0xffffffffu, v, o);
    return v;
}
__device__ __forceinline__ void mma16(float4& c, unsigned a0, unsigned a1, unsigned a2, unsigned a3,
                                      unsigned b0, unsigned b1) {
    asm volatile("mma.sync.aligned.m16n8k16.row.col.f32.f16.f16.f32 "
                 "{%0,%1,%2,%3}, {%4,%5,%6,%7}, {%8,%9}, {%0,%1,%2,%3};\n"
                 : "+f"(c.x), "+f"(c.y), "+f"(c.z), "+f"(c.w)
                 : "r"(a0), "r"(a1), "r"(a2), "r"(a3), "r"(b0), "r"(b1));
}
__device__ __forceinline__ void sth2(__half* p, float x, float y) {
    *reinterpret_cast<__half2*>(p) = __floats2half2_rn(x, y);
}
__device__ __forceinline__ unsigned sptr(const void* p) {
    return (unsigned)__cvta_generic_to_shared(p);
}
__device__ __forceinline__ void ldsm4(unsigned& r0, unsigned& r1, unsigned& r2, unsigned& r3, unsigned addr) {
    asm volatile("ldmatrix.sync.aligned.m8n8.x4.shared.b16 {%0,%1,%2,%3}, [%4];"
                 : "=r"(r0), "=r"(r1), "=r"(r2), "=r"(r3) : "r"(addr));
}
__device__ __forceinline__ void ldsm4t(unsigned& r0, unsigned& r1, unsigned& r2, unsigned& r3, unsigned addr) {
    asm volatile("ldmatrix.sync.aligned.m8n8.x4.trans.shared.b16 {%0,%1,%2,%3}, [%4];"
                 : "=r"(r0), "=r"(r1), "=r"(r2), "=r"(r3) : "r"(addr));
}
__device__ __forceinline__ __half2 h2u(unsigned u) { return *reinterpret_cast<__half2*>(&u); }
__device__ __forceinline__ unsigned hpack(__half2 h) { return *reinterpret_cast<unsigned*>(&h); }

__device__ __forceinline__ void cpa16(unsigned s, const void* g) {
    asm volatile("cp.async.ca.shared.global [%0], [%1], 16;" :: "r"(s), "l"(g) : "memory");
}
#define CPA_COMMIT   asm volatile("cp.async.commit_group;" ::: "memory")
#define CPA_WAIT_ALL asm volatile("cp.async.wait_group 0;" ::: "memory")

__device__ __forceinline__ void stage_slot_async(__half* slot, const __half* g, int tid) {
#pragma unroll
    for (int idx = tid; idx < 512; idx += THREADS) {
        int e = idx >> 3, q = idx & 7;
        cpa16(sptr(slot + e * WP) + q * 16, g + idx * 8);
    }
}

__global__ __launch_bounds__(THREADS, 2)
void cma_fused(const float* __restrict__ feats,
               const float* __restrict__ proj_b, const float* __restrict__ bq,
               const float* __restrict__ bv, const float* __restrict__ bo,
               const float* __restrict__ ng, const float* __restrict__ nb,
               const float* __restrict__ tfw, const float* __restrict__ fg,
               const float* __restrict__ fb, float* __restrict__ out)
{
    extern __shared__ __half smh[];
    __half* sctx  = smh + OFF_CTX;
    __half* slot0 = smh + OFF_W;
    __half* slot1 = smh + OFF_W1;
    __half* bufA  = smh + OFF_A;    // K, then AGG heads
    __half* bufB  = smh + OFF_B;
    float*  abuf  = reinterpret_cast<float*>(smh + OFF_AB);
    float*  obuf  = reinterpret_cast<float*>(smh + OFF_A);

    const int b    = blockIdx.x;
    const int tid  = threadIdx.x;
    const int lane = tid & 31;
    const int wid  = tid >> 5;    // 0..7
    const int lg   = lane >> 2;
    const int lt   = lane & 3;
    const int lm   = lane & 15;
    const int lk8  = (lane >> 4) * 8;

    float wgt[4];
    {
        float t0 = __ldg(tfw + 0), t1 = __ldg(tfw + 1), t2 = __ldg(tfw + 2), t3 = __ldg(tfw + 3);
        float tm = fmaxf(fmaxf(t0, t1), fmaxf(t2, t3));
        float e0 = __expf(t0 - tm), e1 = __expf(t1 - tm), e2 = __expf(t2 - tm), e3 = __expf(t3 - tm);
        float inv = 1.f / (e0 + e1 + e2 + e3);
        wgt[0] = e0 * inv; wgt[1] = e1 * inv; wgt[2] = e2 * inv; wgt[3] = e3 * inv;
    }

    // ================= Phase 1: proj -> sctx[(k*64+d)][t] fp16, LDSM frags =================
    {
        __half* spw   = bufA;              // A: [d][c] pitch PC1
        __half* sfeat = bufA + 64 * PC1;   // B: [c][t] pitch FP
        const int m0 = 16 * (wid & 3);
        const int n0 = 32 * (wid >> 2);
        const unsigned aaddr = sptr(spw + (m0 + lm) * PC1 + lk8);
        const unsigned baddr = sptr(sfeat + lm * FP + n0 + lk8);
        for (int k = 0; k < 4; k++) {
            // spw via cp.async (overlaps with the feats LDG batch below)
#pragma unroll
            for (int idx = tid; idx < 1024; idx += THREADS) {
                int d = idx >> 4, q = idx & 15;
                cpa16(sptr(spw + d * PC1) + q * 16, g_pw + k * 8192 + d * 128 + q * 8);
            }
            CPA_COMMIT;
            const float4* fgl = reinterpret_cast<const float4*>(feats + (size_t)(k * NBLK + b) * 8192);
#pragma unroll
            for (int idx = tid; idx < 2048; idx += THREADS) {
                int c = idx >> 4, q = idx & 15;
                float4 f = fgl[idx];
                __half2 lo = __floats2half2_rn(f.x, f.y);
                __half2 hi = __floats2half2_rn(f.z, f.w);
                uint2 v;
                v.x = hpack(lo);
                v.y = hpack(hi);
                *reinterpret_cast<uint2*>(sfeat + c * FP + 4 * q) = v;
            }
            CPA_WAIT_ALL;
            __syncthreads();

            float4 acc[4] = {{0,0,0,0},{0,0,0,0},{0,0,0,0},{0,0,0,0}};
#pragma unroll
            for (int k0 = 0; k0 < 128; k0 += 16) {
                unsigned a0, a1, a2, a3, b0, b1, b2, b3, c0, c1, c2, c3;
                ldsm4(a0, a1, a2, a3, aaddr + k0 * 2);
                ldsm4t(b0, b1, b2, b3, baddr + k0 * (FP * 2));
                ldsm4t(c0, c1, c2, c3, baddr + k0 * (FP * 2) + 32);
                mma16(acc[0], a0, a1, a2, a3, b0, b1);
                mma16(acc[1], a0, a1, a2, a3, b2, b3);
                mma16(acc[2], a0, a1, a2, a3, c0, c1);
                mma16(acc[3], a0, a1, a2, a3, c2, c3);
            }
            float pb0 = __ldg(proj_b + k * 64 + m0 + lg);
            float pb1 = __ldg(proj_b + k * 64 + m0 + lg + 8);
            __half* crow0 = sctx + (k * 64 + m0 + lg) * CTXP;
            __half* crow1 = crow0 + 8 * CTXP;
#pragma unroll
            for (int j = 0; j < 4; j++) {
                int col = n0 + 8 * j + 2 * lt;
                sth2(crow0 + col, acc[j].x + pb0, acc[j].y + pb0);
                sth2(crow1 + col, acc[j].z + pb1, acc[j].w + pb1);
            }
            __syncthreads();
        }
    }

    // prefetch i=0 weights: wq -> slot0, wk -> slot1
    stage_slot_async(slot0, g_wq, tid);
    stage_slot_async(slot1, g_wk, tid);
    CPA_COMMIT;
    CPA_WAIT_ALL;
    __syncthreads();

    // ================= Phase 2: per-model attention =================
    for (int i = 0; i < 4; i++) {
        // ======== Phase A: G1 (QP) + G2 (K) — independent, one barrier ========
        {
            // G1: QP[r][e'] = bq + q_in @ wq^T -> bufB (m16n32/warp)
            const int m0 = 16 * (wid & 3);
            const int n0 = 32 * (wid >> 2);
            int rA = m0 + lm;
            int jA = ((rA >> 4) << 6) + ((rA & 15) << 2) + i;
            const unsigned aaddr = sptr(sctx + jA * CTXP + lk8);
            const unsigned baddr0 = sptr(slot0 + (n0 + lm) * WP + lk8);
            const unsigned baddr1 = sptr(slot0 + (n0 + 16 + lm) * WP + lk8);
            float4 acc[4] = {{0,0,0,0},{0,0,0,0},{0,0,0,0},{0,0,0,0}};
#pragma unroll
            for (int k0 = 0; k0 < 64; k0 += 16) {
                unsigned a0, a1, a2, a3, p0, p1, p2, p3, q0, q1, q2, q3;
                ldsm4(a0, a1, a2, a3, aaddr + k0 * 2);
                ldsm4(p0, p1, p2, p3, baddr0 + k0 * 2);
                ldsm4(q0, q1, q2, q3, baddr1 + k0 * 2);
                mma16(acc[0], a0, a1, a2, a3, p0, p2);
                mma16(acc[1], a0, a1, a2, a3, p1, p3);
                mma16(acc[2], a0, a1, a2, a3, q0, q2);
                mma16(acc[3], a0, a1, a2, a3, q1, q3);
            }
            __half* crow0 = bufB + (m0 + lg) * BP;
            __half* crow1 = crow0 + 8 * BP;
#pragma unroll
            for (int j = 0; j < 4; j++) {
                int col = n0 + 8 * j + 2 * lt;
                float b0 = __ldg(bq + i * 64 + col), b1 = __ldg(bq + i * 64 + col + 1);
                sth2(crow0 + col, acc[j].x + b0, acc[j].y + b1);
                sth2(crow1 + col, acc[j].z + b0, acc[j].w + b1);
            }

            // G2: K[n][e] = ctx[n] @ wk^T -> bufA (A-frags hoisted once)
            const int warp_m = 32 * wid;
            const unsigned kaaddr0 = sptr(sctx + (warp_m + lm) * CTXP + lk8);
            const unsigned kaaddr1 = sptr(sctx + (warp_m + 16 + lm) * CTXP + lk8);
            unsigned af[2][4][4];
#pragma unroll
            for (int kk = 0; kk < 4; kk++) {
                ldsm4(af[0][kk][0], af[0][kk][1], af[0][kk][2], af[0][kk][3], kaaddr0 + kk * 32);
                ldsm4(af[1][kk][0], af[1][kk][1], af[1][kk][2], af[1][kk][3], kaaddr1 + kk * 32);
            }
#pragma unroll
            for (int nh = 0; nh < 2; nh++) {
                const unsigned kbA = sptr(slot1 + (32 * nh + lm) * WP + lk8);
                const unsigned kbB = sptr(slot1 + (32 * nh + 16 + lm) * WP + lk8);
                float4 kacc[2][4] = {{{0,0,0,0},{0,0,0,0},{0,0,0,0},{0,0,0,0}},
                                     {{0,0,0,0},{0,0,0,0},{0,0,0,0},{0,0,0,0}}};
#pragma unroll
                for (int kk = 0; kk < 4; kk++) {
                    unsigned p0, p1, p2, p3, q0, q1, q2, q3;
                    ldsm4(p0, p1, p2, p3, kbA + kk * 32);
                    ldsm4(q0, q1, q2, q3, kbB + kk * 32);
                    mma16(kacc[0][0], af[0][kk][0], af[0][kk][1], af[0][kk][2], af[0][kk][3], p0, p2);
                    mma16(kacc[0][1], af[0][kk][0], af[0][kk][1], af[0][kk][2], af[0][kk][3], p1, p3);
                    mma16(kacc[0][2], af[0][kk][0], af[0][kk][1], af[0][kk][2], af[0][kk][3], q0, q2);
                    mma16(kacc[0][3], af[0][kk][0], af[0][kk][1], af[0][kk][2], af[0][kk][3], q1, q3);
                    mma16(kacc[1][0], af[1][kk][0], af[1][kk][1], af[1][kk][2], af[1][kk][3], p0, p2);
                    mma16(kacc[1][1], af[1][kk][0], af[1][kk][1], af[1][kk][2], af[1][kk][3], p1, p3);
                    mma16(kacc[1][2], af[1][kk][0], af[1][kk][1], af[1][kk][2], af[1][kk][3], q0, q2);
                    mma16(kacc[1][3], af[1][kk][0], af[1][kk][1], af[1][kk][2], af[1][kk][3], q1, q3);
                }
#pragma unroll
                for (int mt = 0; mt < 2; mt++) {
                    __half* kc0 = bufA + (warp_m + 16 * mt + lg) * CTXP;
                    __half* kc1 = kc0 + 8 * CTXP;
#pragma unroll
                    for (int j = 0; j < 4; j++) {
                        int col = 32 * nh + 8 * j + 2 * lt;
                        sth2(kc0 + col, kacc[mt][j].x, kacc[mt][j].y);
                        sth2(kc1 + col, kacc[mt][j].z, kacc[mt][j].w);
                    }
                }
            }
        }
        __syncthreads();

        // ======== Phase B: prefetch wv->slot0, wo->slot1; G3a scores+softmax ========
        stage_slot_async(slot0, g_wv + i * 4096, tid);
        stage_slot_async(slot1, g_wo + i * 4096, tid);
        CPA_COMMIT;
#pragma unroll
        for (int p = 0; p < 4; p++) {
            int r   = wid * 8 + p * 2 + (lane >> 4);
            int sub = lane & 15;
            int h   = sub >> 2, kp = sub & 3;
            int j   = ((r >> 4) << 6) + ((r & 15) << 2) + kp;
            const uint4* q4 = reinterpret_cast<const uint4*>(bufB + r * BP + 16 * h);
            const uint4* k4 = reinterpret_cast<const uint4*>(bufA + j * CTXP + 16 * h);
            uint4 qa = q4[0], qb = q4[1];
            uint4 ka = k4[0], kb = k4[1];
            __half2 ac0 = __hmul2(h2u(qa.x), h2u(ka.x));
            __half2 ac1 = __hmul2(h2u(qa.y), h2u(ka.y));
            ac0 = __hfma2(h2u(qa.z), h2u(ka.z), ac0);
            ac1 = __hfma2(h2u(qa.w), h2u(ka.w), ac1);
            ac0 = __hfma2(h2u(qb.x), h2u(kb.x), ac0);
            ac1 = __hfma2(h2u(qb.y), h2u(kb.y), ac1);
            ac0 = __hfma2(h2u(qb.z), h2u(kb.z), ac0);
            ac1 = __hfma2(h2u(qb.w), h2u(kb.w), ac1);
            float2 f0 = __half22float2(ac0), f1 = __half22float2(ac1);
            float s = ((f0.x + f0.y) + (f1.x + f1.y)) * 0.25f;
            float m = fmaxf(s, __shfl_xor_sync(0xffffffffu, s, 1));
            m = fmaxf(m, __shfl_xor_sync(0xffffffffu, m, 2));
            float pe  = __expf(s - m);
            float den = pe + __shfl_xor_sync(0xffffffffu, pe, 1);
            den += __shfl_xor_sync(0xffffffffu, den, 2);
            abuf[r * 16 + sub] = pe / den;
        }
        CPA_WAIT_ALL;
        __syncthreads();

        // ======== Phase C: G3b AGG[h][r][t] = sum_kp a * ctx (uint4-wide) ========
        {
            const int rb = (tid >> 3) * 2;    // 0..62 step 2
            const int c8 = (tid & 7) * 8;     // 8-half column group
#pragma unroll
            for (int rr = 0; rr < 2; rr++) {
                int r  = rb + rr;
                int jb = ((r >> 4) << 6) + ((r & 15) << 2);
                uint4 cv[4];
#pragma unroll
                for (int kp = 0; kp < 4; kp++)
                    cv[kp] = *reinterpret_cast<const uint4*>(sctx + (jb + kp) * CTXP + c8);
                const float4* arow = reinterpret_cast<const float4*>(abuf + r * 16);
#pragma unroll
                for (int h = 0; h < 4; h++) {
                    float4 a4 = arow[h];
                    __half2 ac0 = __float2half2_rn(0.f), ac1 = ac0, ac2 = ac0, ac3 = ac0;
#pragma unroll
                    for (int kp = 0; kp < 4; kp++) {
                        __half2 ah = __float2half2_rn((&a4.x)[kp]);
                        ac0 = __hfma2(ah, h2u(cv[kp].x), ac0);
                        ac1 = __hfma2(ah, h2u(cv[kp].y), ac1);
                        ac2 = __hfma2(ah, h2u(cv[kp].z), ac2);
                        ac3 = __hfma2(ah, h2u(cv[kp].w), ac3);
                    }
                    uint4 ov;
                    ov.x = hpack(ac0); ov.y = hpack(ac1);
                    ov.z = hpack(ac2); ov.w = hpack(ac3);
                    *reinterpret_cast<uint4*>(bufA + h * HS + r * CTXP + c8) = ov;
                }
            }
        }
        __syncthreads();

        // ======== Phase D: G4 OA[r][e] = bv + AGG[h(e)] @ wv^T -> bufB (B hoisted) ========
        {
            const int h  = wid >> 1;
            const int mq = wid & 1;
            const unsigned baddr = sptr(slot0 + (16 * h + lm) * WP + lk8);
            const unsigned aaddr0 = sptr(bufA + h * HS + (32 * mq + lm) * CTXP + lk8);
            const unsigned aaddr1 = sptr(bufA + h * HS + (32 * mq + 16 + lm) * CTXP + lk8);
            float4 acc[2][2] = {{{0,0,0,0},{0,0,0,0}},{{0,0,0,0},{0,0,0,0}}};
#pragma unroll
            for (int k0 = 0; k0 < 64; k0 += 16) {
                unsigned p0, p1, p2, p3;
                ldsm4(p0, p1, p2, p3, baddr + k0 * 2);
                unsigned a0, a1, a2, a3;
                ldsm4(a0, a1, a2, a3, aaddr0 + k0 * 2);
                mma16(acc[0][0], a0, a1, a2, a3, p0, p2);
                mma16(acc[0][1], a0, a1, a2, a3, p1, p3);
                ldsm4(a0, a1, a2, a3, aaddr1 + k0 * 2);
                mma16(acc[1][0], a0, a1, a2, a3, p0, p2);
                mma16(acc[1][1], a0, a1, a2, a3, p1, p3);
            }
#pragma unroll
            for (int mt = 0; mt < 2; mt++) {
                const int m0 = 32 * mq + 16 * mt;
                __half* crow0 = bufB + (m0 + lg) * BP;
                __half* crow1 = crow0 + 8 * BP;
#pragma unroll
                for (int j = 0; j < 2; j++) {
                    int col = 16 * h + 8 * j + 2 * lt;
                    float b0 = __ldg(bv + i * 64 + col), b1 = __ldg(bv + i * 64 + col + 1);
                    sth2(crow0 + col, acc[mt][j].x + b0, acc[mt][j].y + b1);
                    sth2(crow1 + col, acc[mt][j].z + b0, acc[mt][j].w + b1);
                }
            }
        }
        __syncthreads();

        // ======== Phase E: G5 O[r][e'] = bo + OA @ wo^T -> obuf fp32 ========
        {
            const int m0 = 16 * (wid & 3);
            const int n0 = 32 * (wid >> 2);
            const unsigned aaddr  = sptr(bufB + (m0 + lm) * BP + lk8);
            const unsigned baddr0 = sptr(slot1 + (n0 + lm) * WP + lk8);
            const unsigned baddr1 = sptr(slot1 + (n0 + 16 + lm) * WP + lk8);
            float4 acc[4] = {{0,0,0,0},{0,0,0,0},{0,0,0,0},{0,0,0,0}};
#pragma unroll
            for (int k0 = 0; k0 < 64; k0 += 16) {
                unsigned a0, a1, a2, a3, p0, p1, p2, p3, q0, q1, q2, q3;
                ldsm4(a0, a1, a2, a3, aaddr + k0 * 2);
                ldsm4(p0, p1, p2, p3, baddr0 + k0 * 2);
                ldsm4(q0, q1, q2, q3, baddr1 + k0 * 2);
                mma16(acc[0], a0, a1, a2, a3, p0, p2);
                mma16(acc[1], a0, a1, a2, a3, p1, p3);
                mma16(acc[2], a0, a1, a2, a3, q0, q2);
                mma16(acc[3], a0, a1, a2, a3, q1, q3);
            }
            float* crow0 = obuf + (m0 + lg) * OP;
            float* crow1 = crow0 + 8 * OP;
#pragma unroll
            for (int j = 0; j < 4; j++) {
                int col = n0 + 8 * j + 2 * lt;
                float b0 = __ldg(bo + i * 64 + col), b1 = __ldg(bo + i * 64 + col + 1);
                crow0[col]     = acc[j].x + b0;
                crow0[col + 1] = acc[j].y + b1;
                crow1[col]     = acc[j].z + b0;
                crow1[col + 1] = acc[j].w + b1;
            }
        }
        __syncthreads();

        // ======== Phase F: LN-64 (+residual), vectorized; prefetch next wq/wk ========
        if (i < 3) {
            stage_slot_async(slot0, g_wq + (i + 1) * 4096, tid);
            stage_slot_async(slot1, g_wk + (i + 1) * 4096, tid);
            CPA_COMMIT;
        }
#pragma unroll
        for (int p = 0; p < 8; p++) {
            int r   = wid * 8 + p;
            int jqr = ((r >> 4) << 6) + ((r & 15) << 2) + i;
            __half2 sx = *reinterpret_cast<const __half2*>(sctx + jqr * CTXP + 2 * lane);
            float2  xo = *reinterpret_cast<const float2*>(obuf + r * OP + 2 * lane);
            float x0 = xo.x + __low2float(sx);
            float x1 = xo.y + __high2float(sx);
            float mean = warp_sum(x0 + x1) * (1.f / 64.f);
            float d0 = x0 - mean, d1 = x1 - mean;
            float var = warp_sum(d0 * d0 + d1 * d1) * (1.f / 64.f);
            float rs = rsqrtf(var + EPSF);
            float2 g2 = __ldg(reinterpret_cast<const float2*>(ng + i * 64 + 2 * lane));
            float2 b2 = __ldg(reinterpret_cast<const float2*>(nb + i * 64 + 2 * lane));
            float2 o;
            o.x = (d0 * rs * g2.x + b2.x) * wgt[i];
            o.y = (d1 * rs * g2.y + b2.y) * wgt[i];
            *reinterpret_cast<float2*>(out + (size_t)b * 16384 + r * 256 + i * 64 + 2 * lane) = o;
        }
        if (i < 3) CPA_WAIT_ALL;
        __syncthreads();
    }

    // ================= Phase 3: final LN over 256, in-place on out =================
    const float4* fg4 = reinterpret_cast<const float4*>(fg);
    const float4* fb4 = reinterpret_cast<const float4*>(fb);
#pragma unroll
    for (int p = 0; p < 8; p++) {
        int r = wid * 8 + p;
        float4* row4 = reinterpret_cast<float4*>(out + (size_t)b * 16384 + r * 256);
        float4 xa = row4[lane], xb = row4[lane + 32];
        float s = xa.x + xa.y + xa.z + xa.w + xb.x + xb.y + xb.z + xb.w;
        float mean = warp_sum(s) * (1.f / 256.f);
        xa.x -= mean; xa.y -= mean; xa.z -= mean; xa.w -= mean;
        xb.x -= mean; xb.y -= mean; xb.z -= mean; xb.w -= mean;
        float v = xa.x*xa.x + xa.y*xa.y + xa.z*xa.z + xa.w*xa.w
                + xb.x*xb.x + xb.y*xb.y + xb.z*xb.z + xb.w*xb.w;
        float var = warp_sum(v) * (1.f / 256.f);
        float rs = rsqrtf(var + EPSF);
        float4 ga = fg4[lane], gb = fg4[lane + 32];
        float4 ba = fb4[lane], bb = fb4[lane + 32];
        row4[lane]      = make_float4(fmaf(xa.x * rs, ga.x, ba.x), fmaf(xa.y * rs, ga.y, ba.y),
                                      fmaf(xa.z * rs, ga.z, ba.z), fmaf(xa.w * rs, ga.w, ba.w));
        row4[lane + 32] = make_float4(fmaf(xb.x * rs, gb.x, bb.x), fmaf(xb.y * rs, gb.y, bb.y),
                                      fmaf(xb.z * rs, gb.z, bb.z), fmaf(xb.w * rs, gb.w, bb.w));
    }
}

extern "C" void kernel_launch(void* const* d_in, const int* in_sizes, int n_in,
                              void* d_out, int out_size) {
    (void)in_sizes; (void)n_in; (void)out_size;
    const float* feats  = (const float*)d_in[0];
    const float* proj_w = (const float*)d_in[1];
    const float* proj_b = (const float*)d_in[2];
    const float* wq     = (const float*)d_in[3];
    const float* wk     = (const float*)d_in[4];
    const float* wv     = (const float*)d_in[5];
    const float* bq     = (const float*)d_in[6];
    const float* bv     = (const float*)d_in[8];
    const float* wo     = (const float*)d_in[9];
    const float* bo     = (const float*)d_in[10];
    const float* ng     = (const float*)d_in[11];
    const float* nb     = (const float*)d_in[12];
    const float* tfw    = (const float*)d_in[13];
    const float* fg     = (const float*)d_in[14];
    const float* fb     = (const float*)d_in[15];
    float* out = (float*)d_out;

    prep_weights<<<64, 256>>>(proj_w, wq, wk, wv, wo);

    size_t smem = SMEM_HALVES * sizeof(__half);
    cudaFuncSetAttribute(cma_fused, cudaFuncAttributeMaxDynamicSharedMemorySize, (int)smem);
    cma_fused<<<NBLK, THREADS, smem>>>(feats, proj_b, bq, bv, bo,
                                       ng, nb, tfw, fg, fb, out);
}